// round 13
// baseline (speedup 1.0000x reference)
#include <cuda_runtime.h>
#include <cuda_bf16.h>
#include <cuda_pipeline.h>
#include <mma.h>
#include <cstdint>

using namespace nvcuda;

// Problem constants (fixed by dataset)
#define DFEAT 512
#define NOUT  64
#define GROWS 96              // gemm rows per block
#define MAXN  100032          // N_NODES rounded up: divisible by 96 (96*1042)
#define NPAD  102400          // node arrays padded to 1024*100 for scan tiles
#define MAXE  1600000
#define NBLK_SCAN 100         // NPAD / 1024

// Static device scratch (no runtime allocation allowed)
__device__ float          g_h[(size_t)MAXN * NOUT];   // projected features (25.6 MB)
__device__ __nv_bfloat16  g_Wh16[DFEAT * NOUT];       // W hi bf16, [k][n]
__device__ __nv_bfloat16  g_Wl16[DFEAT * NOUT];       // W lo residual bf16, [k][n]
__device__ uint2          g_pairs[MAXE];              // (src, w-bits) grouped by dst
__device__ int            g_cnt[NPAD];                // per-dst degree
__device__ int            g_start[NPAD];              // CSR row start
__device__ int            g_cursor[NPAD];             // fill cursor == row end
__device__ unsigned int   g_tilestate[NBLK_SCAN];     // lookback: flag<<30 | sum

// ---------------------------------------------------------------------------
// Step 1 (one kernel): presplit W + zero histogram + zero scan state.
// Graph is replayed, so all mutable state must be reset every call.
// ---------------------------------------------------------------------------
__global__ void setup_kernel(const float* __restrict__ W) {
    int i = blockIdx.x * blockDim.x + threadIdx.x;
    if (i < DFEAT * NOUT) {
        float w = __ldg(&W[i]);
        uint32_t u = __float_as_uint(w);
        unsigned short hb = (unsigned short)(u >> 16);        // truncated bf16
        g_Wh16[i] = *reinterpret_cast<__nv_bfloat16*>(&hb);
        float lo = w - __uint_as_float(u & 0xFFFF0000u);
        g_Wl16[i] = __float2bfloat16_rn(lo);
    }
    if (i < NPAD / 4) ((int4*)g_cnt)[i] = make_int4(0, 0, 0, 0);
    if (i < NBLK_SCAN) g_tilestate[i] = 0u;
}

// ---------------------------------------------------------------------------
// Step 2: degree histogram over dst
// ---------------------------------------------------------------------------
__global__ void hist_kernel(const int* __restrict__ edst, int n_edges) {
    int e = blockIdx.x * blockDim.x + threadIdx.x;
    if (e < n_edges) atomicAdd(&g_cnt[__ldg(&edst[e])], 1);
}

// ---------------------------------------------------------------------------
// Step 3: single-pass exclusive scan (decoupled lookback), 1024 nodes/block.
// ---------------------------------------------------------------------------
__global__ void __launch_bounds__(256) scan_onepass_kernel() {
    const int b   = blockIdx.x;
    const int tid = threadIdx.x;
    const int idx = b * 1024 + tid * 4;

    int4 c = *(const int4*)&g_cnt[idx];
    int t = c.x + c.y + c.z + c.w;

    int incl = t;
#pragma unroll
    for (int o = 1; o < 32; o <<= 1) {
        int u = __shfl_up_sync(0xffffffffu, incl, o);
        if ((tid & 31) >= o) incl += u;
    }
    __shared__ int wsum[8];
    __shared__ int s_excl;
    if ((tid & 31) == 31) wsum[tid >> 5] = incl;
    __syncthreads();

    const int wid = tid >> 5;
    int off = 0, agg = 0;
#pragma unroll
    for (int i = 0; i < 8; ++i) {
        int v = wsum[i];
        if (i < wid) off += v;
        agg += v;
    }

    if (tid == 0) {
        if (b == 0) {
            atomicExch(&g_tilestate[0], (2u << 30) | (unsigned)agg);
            s_excl = 0;
        } else {
            atomicExch(&g_tilestate[b], (1u << 30) | (unsigned)agg);
            int run = 0, p = b - 1;
            while (true) {
                unsigned s;
                do { s = atomicAdd(&g_tilestate[p], 0u); } while ((s >> 30) == 0u);
                run += (int)(s & 0x3fffffffu);
                if ((s >> 30) == 2u) break;
                --p;
            }
            atomicExch(&g_tilestate[b], (2u << 30) | (unsigned)(run + agg));
            s_excl = run;
        }
    }
    __syncthreads();

    int s0 = s_excl + (incl - t) + off;
    int4 st;
    st.x = s0; st.y = s0 + c.x; st.z = st.y + c.y; st.w = st.z + c.z;
    *(int4*)&g_start[idx]  = st;
    *(int4*)&g_cursor[idx] = st;
}

// ---------------------------------------------------------------------------
// pack2: (f0,f1) -> packed bf16x2 hi (truncated, via PRMT) + bf16x2 lo
// ---------------------------------------------------------------------------
__device__ __forceinline__ void pack2(float f0, float f1, uint32_t& hp, uint32_t& lp) {
    uint32_t u0 = __float_as_uint(f0), u1 = __float_as_uint(f1);
    hp = __byte_perm(u0, u1, 0x7632);                 // (hi16(f0), hi16(f1))
    float l0 = f0 - __uint_as_float(u0 & 0xFFFF0000u);
    float l1 = f1 - __uint_as_float(u1 & 0xFFFF0000u);
    __nv_bfloat162 l2 = __floats2bfloat162_rn(l0, l1);
    lp = *reinterpret_cast<uint32_t*>(&l2);
}

// ---------------------------------------------------------------------------
// Step 4 (slot 4 -> profiled): GEMM h = x @ W, split-bf16 HMMA (3-term).
// h = xh*Wh + xh*Wl + xl*Wh, fp32 acc.
// Tile 96x64, BK=32, 192 threads = 6 warps (3x2), warp tile 32x32 (2x2 accs).
// R12 change: __launch_bounds__(192,4) for 4 CTAs/SM (occ 24->37%); address
// state rematerialized per prefetch instead of held in registers.
// ---------------------------------------------------------------------------
__global__ void __launch_bounds__(192, 4) gemm_kernel(const float* __restrict__ x,
                                                      int n_rows)
{
    __shared__ __align__(16) __nv_bfloat16 xs_hi[GROWS][40];  // 96 rows x 32 k (+pad)
    __shared__ __align__(16) __nv_bfloat16 xs_lo[GROWS][40];
    __shared__ __align__(16) __nv_bfloat16 ws_hi[32][72];     // 32 k x 64 n (+pad)
    __shared__ __align__(16) __nv_bfloat16 ws_lo[32][72];

    const int tid  = threadIdx.x;
    const int row0 = blockIdx.x * GROWS;

    const int wid    = tid >> 5;
    const int warp_r = (wid >> 1) * 32;   // 0,32,64
    const int warp_c = (wid & 1) * 32;    // 0,32

    wmma::fragment<wmma::accumulator, 16, 16, 16, float> acc[2][2];
#pragma unroll
    for (int i = 0; i < 2; ++i)
#pragma unroll
        for (int j = 0; j < 2; ++j)
            wmma::fill_fragment(acc[i][j], 0.0f);

    // x loader mapping: 768 float4 per tile (96 rows x 8), 4 per thread.
    // f = tid + p*192: row = f>>3, k4 = (f&7)*4. Addresses recomputed per
    // prefetch (rematerializable ALU) instead of held across the loop.
    float4 xv[4];
#pragma unroll
    for (int p = 0; p < 4; ++p) {
        int f = tid + p * 192;
        int gr = row0 + (f >> 3);
        if (gr >= n_rows) gr = n_rows - 1;           // clamp: dup rows, never gathered
        xv[p] = *(const float4*)(x + (size_t)gr * DFEAT + (f & 7) * 4);
    }

    const int KT = DFEAT / 32;
    for (int kt = 0; kt < KT; ++kt) {
        // stage x: truncation split + packed 8B stores
#pragma unroll
        for (int p = 0; p < 4; ++p) {
            int f = tid + p * 192;
            int r = f >> 3;
            int k4 = (f & 7) * 4;
            uint32_t h0, l0, h1, l1;
            pack2(xv[p].x, xv[p].y, h0, l0);
            pack2(xv[p].z, xv[p].w, h1, l1);
            *(uint2*)&xs_hi[r][k4] = make_uint2(h0, h1);
            *(uint2*)&xs_lo[r][k4] = make_uint2(l0, l1);
        }
        // stage W via cp.async: 512 16B chunks (256 hi + 256 lo)
        for (int g = tid; g < 512; g += 192) {
            int hi = (g < 256);
            int gg = g & 255;
            int r  = gg >> 3;                 // k row 0..31
            int c8 = (gg & 7) * 8;            // 8 bf16 per chunk
            const __nv_bfloat16* src = (hi ? g_Wh16 : g_Wl16) + (size_t)(kt * 32 + r) * NOUT + c8;
            __nv_bfloat16* dst = (hi ? &ws_hi[r][c8] : &ws_lo[r][c8]);
            __pipeline_memcpy_async(dst, src, 16);
        }
        __pipeline_commit();

        // prefetch next x tile into registers (addresses rematerialized)
        if (kt + 1 < KT) {
#pragma unroll
            for (int p = 0; p < 4; ++p) {
                int f = tid + p * 192;
                int gr = row0 + (f >> 3);
                if (gr >= n_rows) gr = n_rows - 1;
                xv[p] = *(const float4*)(x + (size_t)gr * DFEAT + (kt + 1) * 32 + (f & 7) * 4);
            }
        }

        __pipeline_wait_prior(0);
        __syncthreads();

#pragma unroll
        for (int ks = 0; ks < 2; ++ks) {
            const int k0 = ks * 16;
            wmma::fragment<wmma::matrix_a, 16, 16, 16, __nv_bfloat16, wmma::row_major> a_hi[2], a_lo[2];
#pragma unroll
            for (int i = 0; i < 2; ++i) {
                wmma::load_matrix_sync(a_hi[i], &xs_hi[warp_r + i * 16][k0], 40);
                wmma::load_matrix_sync(a_lo[i], &xs_lo[warp_r + i * 16][k0], 40);
            }
#pragma unroll
            for (int j = 0; j < 2; ++j) {
                wmma::fragment<wmma::matrix_b, 16, 16, 16, __nv_bfloat16, wmma::row_major> b_hi, b_lo;
                wmma::load_matrix_sync(b_hi, &ws_hi[k0][warp_c + j * 16], 72);
                wmma::load_matrix_sync(b_lo, &ws_lo[k0][warp_c + j * 16], 72);
#pragma unroll
                for (int i = 0; i < 2; ++i) {
                    wmma::mma_sync(acc[i][j], a_hi[i], b_hi, acc[i][j]);
                    wmma::mma_sync(acc[i][j], a_hi[i], b_lo, acc[i][j]);
                    wmma::mma_sync(acc[i][j], a_lo[i], b_hi, acc[i][j]);
                }
            }
        }
        __syncthreads();
    }

    // g_h padded to MAXN (multiple of 96): full-tile stores stay in bounds.
#pragma unroll
    for (int i = 0; i < 2; ++i)
#pragma unroll
        for (int j = 0; j < 2; ++j)
            wmma::store_matrix_sync(
                g_h + (size_t)(row0 + warp_r + i * 16) * NOUT + warp_c + j * 16,
                acc[i][j], NOUT, wmma::mem_row_major);
}

// ---------------------------------------------------------------------------
// Step 5: reorder edges into dst-grouped (src, w) pairs.
// ---------------------------------------------------------------------------
__global__ void __launch_bounds__(256) reorder_kernel(const int*   __restrict__ esrc,
                                                      const int*   __restrict__ edst,
                                                      const float* __restrict__ ew,
                                                      int n_edges)
{
    int e = blockIdx.x * blockDim.x + threadIdx.x;
    if (e >= n_edges) return;
    int d = __ldg(&edst[e]);
    int pos = atomicAdd(&g_cursor[d], 1);
    g_pairs[pos] = make_uint2((unsigned)__ldg(&esrc[e]), __float_as_uint(__ldg(&ew[e])));
}

// ---------------------------------------------------------------------------
// Step 6: gather + fused softmax. One warp per dst node, lane owns 2 channels.
// ---------------------------------------------------------------------------
__global__ void __launch_bounds__(256) gather_softmax_kernel(float* __restrict__ out,
                                                             int n_nodes)
{
    int node = blockIdx.x * 8 + (threadIdx.x >> 5);
    int lane = threadIdx.x & 31;
    if (node >= n_nodes) return;

    int start = __ldg(&g_start[node]);
    int end   = __ldg(&g_cursor[node]);

    float2 acc = make_float2(0.f, 0.f);

    for (int base = start; base < end; base += 32) {
        int idx = base + lane;
        uint2 pr = make_uint2(0u, 0u);
        if (idx < end) pr = __ldg(&g_pairs[idx]);
        int m = end - base; if (m > 32) m = 32;

        int j = 0;
        for (; j + 8 <= m; j += 8) {
#pragma unroll
            for (int u = 0; u < 8; ++u) {
                int   ss = __shfl_sync(0xffffffffu, (int)pr.x, j + u);
                float sw = __uint_as_float(__shfl_sync(0xffffffffu, pr.y, j + u));
                float2 hv = *(const float2*)(g_h + (size_t)ss * NOUT + (lane << 1));
                acc.x = fmaf(sw, hv.x, acc.x);
                acc.y = fmaf(sw, hv.y, acc.y);
            }
        }
        for (; j < m; ++j) {
            int   ss = __shfl_sync(0xffffffffu, (int)pr.x, j);
            float sw = __uint_as_float(__shfl_sync(0xffffffffu, pr.y, j));
            float2 hv = *(const float2*)(g_h + (size_t)ss * NOUT + (lane << 1));
            acc.x = fmaf(sw, hv.x, acc.x);
            acc.y = fmaf(sw, hv.y, acc.y);
        }
    }

    float mx = fmaxf(acc.x, acc.y);
#pragma unroll
    for (int o = 16; o > 0; o >>= 1)
        mx = fmaxf(mx, __shfl_xor_sync(0xffffffffu, mx, o));

    float e0 = __expf(acc.x - mx);
    float e1 = __expf(acc.y - mx);
    float s = e0 + e1;
#pragma unroll
    for (int o = 16; o > 0; o >>= 1)
        s += __shfl_xor_sync(0xffffffffu, s, o);

    float inv = 1.0f / s;
    *(float2*)&out[(size_t)node * NOUT + (lane << 1)] = make_float2(e0 * inv, e1 * inv);
}

// ---------------------------------------------------------------------------
// Launch. Input order per metadata: x, edge_src, edge_dst, edge_w, W.
// GEMM kept at launch slot 4 (ncu captures launch #4).
// ---------------------------------------------------------------------------
extern "C" void kernel_launch(void* const* d_in, const int* in_sizes, int n_in,
                              void* d_out, int out_size)
{
    const float* x    = (const float*)d_in[0];
    const int*   esrc = (const int*)  d_in[1];
    const int*   edst = (const int*)  d_in[2];
    const float* ew   = (const float*)d_in[3];
    const float* W    = (const float*)d_in[4];
    float*       out  = (float*)d_out;

    const int n_nodes = in_sizes[0] / DFEAT;
    const int n_edges = in_sizes[1];
    const int eblk    = (n_edges + 255) / 256;
    const int ntiles  = (n_nodes + 1023) / 1024;

    setup_kernel<<<(DFEAT * NOUT + 255) / 256, 256>>>(W);                // 1
    hist_kernel<<<eblk, 256>>>(edst, n_edges);                           // 2
    scan_onepass_kernel<<<ntiles, 256>>>();                              // 3
    gemm_kernel<<<(n_nodes + GROWS - 1) / GROWS, 192>>>(x, n_nodes);     // 4 (profiled)
    reorder_kernel<<<eblk, 256>>>(esrc, edst, ew, n_edges);              // 5
    gather_softmax_kernel<<<(n_nodes + 7) / 8, 256>>>(out, n_nodes);     // 6
}

// round 14
// speedup vs baseline: 1.1523x; 1.1523x over previous
#include <cuda_runtime.h>
#include <cuda_bf16.h>
#include <cuda_pipeline.h>
#include <mma.h>
#include <cstdint>

using namespace nvcuda;

// Problem constants (fixed by dataset)
#define DFEAT 512
#define NOUT  64
#define GROWS 96              // gemm rows per block
#define MAXN  100032          // N_NODES rounded up: divisible by 96 (96*1042)
#define NPAD  102400          // node arrays padded to 1024*100 for scan tiles
#define MAXE  1600000
#define NBLK_SCAN 100         // NPAD / 1024

// Static device scratch (no runtime allocation allowed)
__device__ float          g_h[(size_t)MAXN * NOUT];   // projected features (25.6 MB)
__device__ __nv_bfloat16  g_Wh16[DFEAT * NOUT];       // W hi bf16, [k][n]
__device__ __nv_bfloat16  g_Wl16[DFEAT * NOUT];       // W lo residual bf16, [k][n]
__device__ uint2          g_pairs[MAXE];              // (src, w-bits) grouped by dst
__device__ int            g_cnt[NPAD];                // per-dst degree
__device__ int            g_start[NPAD];              // CSR row start
__device__ int            g_cursor[NPAD];             // fill cursor == row end
__device__ unsigned int   g_tilestate[NBLK_SCAN];     // lookback: flag<<30 | sum

// ---------------------------------------------------------------------------
// Step 1 (one kernel): presplit W + zero histogram + zero scan state.
// Graph is replayed, so all mutable state must be reset every call.
// ---------------------------------------------------------------------------
__global__ void setup_kernel(const float* __restrict__ W) {
    int i = blockIdx.x * blockDim.x + threadIdx.x;
    if (i < DFEAT * NOUT) {
        float w = __ldg(&W[i]);
        uint32_t u = __float_as_uint(w);
        unsigned short hb = (unsigned short)(u >> 16);        // truncated bf16
        g_Wh16[i] = *reinterpret_cast<__nv_bfloat16*>(&hb);
        float lo = w - __uint_as_float(u & 0xFFFF0000u);
        g_Wl16[i] = __float2bfloat16_rn(lo);
    }
    if (i < NPAD / 4) ((int4*)g_cnt)[i] = make_int4(0, 0, 0, 0);
    if (i < NBLK_SCAN) g_tilestate[i] = 0u;
}

// ---------------------------------------------------------------------------
// Step 2: degree histogram over dst — 4 edges per thread via int4 load.
// ---------------------------------------------------------------------------
__global__ void hist_kernel(const int* __restrict__ edst, int n_edges) {
    int t = blockIdx.x * blockDim.x + threadIdx.x;
    int e = t * 4;
    if (e + 3 < n_edges) {
        int4 d = *(const int4*)(edst + e);
        atomicAdd(&g_cnt[d.x], 1);
        atomicAdd(&g_cnt[d.y], 1);
        atomicAdd(&g_cnt[d.z], 1);
        atomicAdd(&g_cnt[d.w], 1);
    } else {
        for (int k = e; k < n_edges; ++k) atomicAdd(&g_cnt[__ldg(&edst[k])], 1);
    }
}

// ---------------------------------------------------------------------------
// Step 3: single-pass exclusive scan (decoupled lookback), 1024 nodes/block.
// ---------------------------------------------------------------------------
__global__ void __launch_bounds__(256) scan_onepass_kernel() {
    const int b   = blockIdx.x;
    const int tid = threadIdx.x;
    const int idx = b * 1024 + tid * 4;

    int4 c = *(const int4*)&g_cnt[idx];
    int t = c.x + c.y + c.z + c.w;

    int incl = t;
#pragma unroll
    for (int o = 1; o < 32; o <<= 1) {
        int u = __shfl_up_sync(0xffffffffu, incl, o);
        if ((tid & 31) >= o) incl += u;
    }
    __shared__ int wsum[8];
    __shared__ int s_excl;
    if ((tid & 31) == 31) wsum[tid >> 5] = incl;
    __syncthreads();

    const int wid = tid >> 5;
    int off = 0, agg = 0;
#pragma unroll
    for (int i = 0; i < 8; ++i) {
        int v = wsum[i];
        if (i < wid) off += v;
        agg += v;
    }

    if (tid == 0) {
        if (b == 0) {
            atomicExch(&g_tilestate[0], (2u << 30) | (unsigned)agg);
            s_excl = 0;
        } else {
            atomicExch(&g_tilestate[b], (1u << 30) | (unsigned)agg);
            int run = 0, p = b - 1;
            while (true) {
                unsigned s;
                do { s = atomicAdd(&g_tilestate[p], 0u); } while ((s >> 30) == 0u);
                run += (int)(s & 0x3fffffffu);
                if ((s >> 30) == 2u) break;
                --p;
            }
            atomicExch(&g_tilestate[b], (2u << 30) | (unsigned)(run + agg));
            s_excl = run;
        }
    }
    __syncthreads();

    int s0 = s_excl + (incl - t) + off;
    int4 st;
    st.x = s0; st.y = s0 + c.x; st.z = st.y + c.y; st.w = st.z + c.z;
    *(int4*)&g_start[idx]  = st;
    *(int4*)&g_cursor[idx] = st;
}

// ---------------------------------------------------------------------------
// Step 4 (slot 4 -> profiled this round): reorder edges into dst-grouped
// (src, w) pairs — 2 edges per thread via vectorized loads.
// ---------------------------------------------------------------------------
__global__ void __launch_bounds__(256) reorder_kernel(const int*   __restrict__ esrc,
                                                      const int*   __restrict__ edst,
                                                      const float* __restrict__ ew,
                                                      int n_edges)
{
    int t = blockIdx.x * blockDim.x + threadIdx.x;
    int e = t * 2;
    if (e + 1 < n_edges) {
        int2   s = *(const int2*)(esrc + e);
        int2   d = *(const int2*)(edst + e);
        float2 w = *(const float2*)(ew + e);
        int p0 = atomicAdd(&g_cursor[d.x], 1);
        g_pairs[p0] = make_uint2((unsigned)s.x, __float_as_uint(w.x));
        int p1 = atomicAdd(&g_cursor[d.y], 1);
        g_pairs[p1] = make_uint2((unsigned)s.y, __float_as_uint(w.y));
    } else if (e < n_edges) {
        int d = __ldg(&edst[e]);
        int pos = atomicAdd(&g_cursor[d], 1);
        g_pairs[pos] = make_uint2((unsigned)__ldg(&esrc[e]), __float_as_uint(__ldg(&ew[e])));
    }
}

// ---------------------------------------------------------------------------
// pack2: (f0,f1) -> packed bf16x2 hi (truncated, via PRMT) + bf16x2 lo
// ---------------------------------------------------------------------------
__device__ __forceinline__ void pack2(float f0, float f1, uint32_t& hp, uint32_t& lp) {
    uint32_t u0 = __float_as_uint(f0), u1 = __float_as_uint(f1);
    hp = __byte_perm(u0, u1, 0x7632);                 // (hi16(f0), hi16(f1))
    float l0 = f0 - __uint_as_float(u0 & 0xFFFF0000u);
    float l1 = f1 - __uint_as_float(u1 & 0xFFFF0000u);
    __nv_bfloat162 l2 = __floats2bfloat162_rn(l0, l1);
    lp = *reinterpret_cast<uint32_t*>(&l2);
}

// ---------------------------------------------------------------------------
// Step 5: GEMM h = x @ W, split-bf16 HMMA (3-term) — exact R11 configuration
// (196.8us total, GEMM 106.6us). h = xh*Wh + xh*Wl + xl*Wh, fp32 acc.
// Tile 96x64, BK=32, 192 threads = 6 warps (3x2), warp tile 32x32 (2x2 accs),
// 3 CTAs/SM. W staged via cp.async; x truncation-split packed STS.
// ---------------------------------------------------------------------------
__global__ void __launch_bounds__(192, 3) gemm_kernel(const float* __restrict__ x,
                                                      int n_rows)
{
    __shared__ __align__(16) __nv_bfloat16 xs_hi[GROWS][40];  // 96 rows x 32 k (+pad)
    __shared__ __align__(16) __nv_bfloat16 xs_lo[GROWS][40];
    __shared__ __align__(16) __nv_bfloat16 ws_hi[32][72];     // 32 k x 64 n (+pad)
    __shared__ __align__(16) __nv_bfloat16 ws_lo[32][72];

    const int tid  = threadIdx.x;
    const int row0 = blockIdx.x * GROWS;

    const int wid    = tid >> 5;
    const int warp_r = (wid >> 1) * 32;   // 0,32,64
    const int warp_c = (wid & 1) * 32;    // 0,32

    wmma::fragment<wmma::accumulator, 16, 16, 16, float> acc[2][2];
#pragma unroll
    for (int i = 0; i < 2; ++i)
#pragma unroll
        for (int j = 0; j < 2; ++j)
            wmma::fill_fragment(acc[i][j], 0.0f);

    // x loader mapping: 768 float4 per tile (96 rows x 8), 4 per thread.
    float4 xv[4];
    int  xrow[4];
#pragma unroll
    for (int p = 0; p < 4; ++p) {
        int f = tid + p * 192;
        int r = f >> 3;
        int gr = row0 + r;
        if (gr >= n_rows) gr = n_rows - 1;           // clamp: dup rows, never gathered
        xrow[p] = gr;
        xv[p] = *(const float4*)(x + (size_t)gr * DFEAT + (f & 7) * 4);
    }

    const int KT = DFEAT / 32;
    for (int kt = 0; kt < KT; ++kt) {
        // stage x: truncation split + packed 8B stores
#pragma unroll
        for (int p = 0; p < 4; ++p) {
            int f = tid + p * 192;
            int r = f >> 3;
            int k4 = (f & 7) * 4;
            uint32_t h0, l0, h1, l1;
            pack2(xv[p].x, xv[p].y, h0, l0);
            pack2(xv[p].z, xv[p].w, h1, l1);
            *(uint2*)&xs_hi[r][k4] = make_uint2(h0, h1);
            *(uint2*)&xs_lo[r][k4] = make_uint2(l0, l1);
        }
        // stage W via cp.async: 512 16B chunks (256 hi + 256 lo)
        for (int g = tid; g < 512; g += 192) {
            int hi = (g < 256);
            int gg = g & 255;
            int r  = gg >> 3;                 // k row 0..31
            int c8 = (gg & 7) * 8;            // 8 bf16 per chunk
            const __nv_bfloat16* src = (hi ? g_Wh16 : g_Wl16) + (size_t)(kt * 32 + r) * NOUT + c8;
            __nv_bfloat16* dst = (hi ? &ws_hi[r][c8] : &ws_lo[r][c8]);
            __pipeline_memcpy_async(dst, src, 16);
        }
        __pipeline_commit();

        // prefetch next x tile into registers (overlaps cp.async)
        if (kt + 1 < KT) {
#pragma unroll
            for (int p = 0; p < 4; ++p) {
                int f = tid + p * 192;
                xv[p] = *(const float4*)(x + (size_t)xrow[p] * DFEAT + (kt + 1) * 32 + (f & 7) * 4);
            }
        }

        __pipeline_wait_prior(0);
        __syncthreads();

#pragma unroll
        for (int ks = 0; ks < 2; ++ks) {
            const int k0 = ks * 16;
            wmma::fragment<wmma::matrix_a, 16, 16, 16, __nv_bfloat16, wmma::row_major> a_hi[2], a_lo[2];
#pragma unroll
            for (int i = 0; i < 2; ++i) {
                wmma::load_matrix_sync(a_hi[i], &xs_hi[warp_r + i * 16][k0], 40);
                wmma::load_matrix_sync(a_lo[i], &xs_lo[warp_r + i * 16][k0], 40);
            }
#pragma unroll
            for (int j = 0; j < 2; ++j) {
                wmma::fragment<wmma::matrix_b, 16, 16, 16, __nv_bfloat16, wmma::row_major> b_hi, b_lo;
                wmma::load_matrix_sync(b_hi, &ws_hi[k0][warp_c + j * 16], 72);
                wmma::load_matrix_sync(b_lo, &ws_lo[k0][warp_c + j * 16], 72);
#pragma unroll
                for (int i = 0; i < 2; ++i) {
                    wmma::mma_sync(acc[i][j], a_hi[i], b_hi, acc[i][j]);
                    wmma::mma_sync(acc[i][j], a_hi[i], b_lo, acc[i][j]);
                    wmma::mma_sync(acc[i][j], a_lo[i], b_hi, acc[i][j]);
                }
            }
        }
        __syncthreads();
    }

    // g_h padded to MAXN (multiple of 96): full-tile stores stay in bounds.
#pragma unroll
    for (int i = 0; i < 2; ++i)
#pragma unroll
        for (int j = 0; j < 2; ++j)
            wmma::store_matrix_sync(
                g_h + (size_t)(row0 + warp_r + i * 16) * NOUT + warp_c + j * 16,
                acc[i][j], NOUT, wmma::mem_row_major);
}

// ---------------------------------------------------------------------------
// Step 6: gather + fused softmax. One warp per dst node, lane owns 2 channels.
// ---------------------------------------------------------------------------
__global__ void __launch_bounds__(256) gather_softmax_kernel(float* __restrict__ out,
                                                             int n_nodes)
{
    int node = blockIdx.x * 8 + (threadIdx.x >> 5);
    int lane = threadIdx.x & 31;
    if (node >= n_nodes) return;

    int start = __ldg(&g_start[node]);
    int end   = __ldg(&g_cursor[node]);

    float2 acc = make_float2(0.f, 0.f);

    for (int base = start; base < end; base += 32) {
        int idx = base + lane;
        uint2 pr = make_uint2(0u, 0u);
        if (idx < end) pr = __ldg(&g_pairs[idx]);
        int m = end - base; if (m > 32) m = 32;

        int j = 0;
        for (; j + 8 <= m; j += 8) {
#pragma unroll
            for (int u = 0; u < 8; ++u) {
                int   ss = __shfl_sync(0xffffffffu, (int)pr.x, j + u);
                float sw = __uint_as_float(__shfl_sync(0xffffffffu, pr.y, j + u));
                float2 hv = *(const float2*)(g_h + (size_t)ss * NOUT + (lane << 1));
                acc.x = fmaf(sw, hv.x, acc.x);
                acc.y = fmaf(sw, hv.y, acc.y);
            }
        }
        for (; j < m; ++j) {
            int   ss = __shfl_sync(0xffffffffu, (int)pr.x, j);
            float sw = __uint_as_float(__shfl_sync(0xffffffffu, pr.y, j));
            float2 hv = *(const float2*)(g_h + (size_t)ss * NOUT + (lane << 1));
            acc.x = fmaf(sw, hv.x, acc.x);
            acc.y = fmaf(sw, hv.y, acc.y);
        }
    }

    float mx = fmaxf(acc.x, acc.y);
#pragma unroll
    for (int o = 16; o > 0; o >>= 1)
        mx = fmaxf(mx, __shfl_xor_sync(0xffffffffu, mx, o));

    float e0 = __expf(acc.x - mx);
    float e1 = __expf(acc.y - mx);
    float s = e0 + e1;
#pragma unroll
    for (int o = 16; o > 0; o >>= 1)
        s += __shfl_xor_sync(0xffffffffu, s, o);

    float inv = 1.0f / s;
    *(float2*)&out[(size_t)node * NOUT + (lane << 1)] = make_float2(e0 * inv, e1 * inv);
}

// ---------------------------------------------------------------------------
// Launch. Input order per metadata: x, edge_src, edge_dst, edge_w, W.
// reorder_kernel at launch slot 4 this round (ncu captures launch #4);
// gemm moved to slot 5 (its profile is known from R11: 106.6us).
// Dependencies: setup->gemm; hist->scan->reorder; (gemm,reorder)->gather. OK.
// ---------------------------------------------------------------------------
extern "C" void kernel_launch(void* const* d_in, const int* in_sizes, int n_in,
                              void* d_out, int out_size)
{
    const float* x    = (const float*)d_in[0];
    const int*   esrc = (const int*)  d_in[1];
    const int*   edst = (const int*)  d_in[2];
    const float* ew   = (const float*)d_in[3];
    const float* W    = (const float*)d_in[4];
    float*       out  = (float*)d_out;

    const int n_nodes = in_sizes[0] / DFEAT;
    const int n_edges = in_sizes[1];
    const int ntiles  = (n_nodes + 1023) / 1024;
    const int hblk    = (n_edges / 4 + 256) / 256;   // 4 edges/thread
    const int rblk    = (n_edges / 2 + 256) / 256;   // 2 edges/thread

    setup_kernel<<<(DFEAT * NOUT + 255) / 256, 256>>>(W);                // 1
    hist_kernel<<<hblk, 256>>>(edst, n_edges);                           // 2
    scan_onepass_kernel<<<ntiles, 256>>>();                              // 3
    reorder_kernel<<<rblk, 256>>>(esrc, edst, ew, n_edges);              // 4 (profiled)
    gemm_kernel<<<(n_nodes + GROWS - 1) / GROWS, 192>>>(x, n_nodes);     // 5
    gather_softmax_kernel<<<(n_nodes + 7) / 8, 256>>>(out, n_nodes);     // 6
}

// round 15
// speedup vs baseline: 1.3132x; 1.1396x over previous
#include <cuda_runtime.h>
#include <cuda_bf16.h>
#include <cuda_pipeline.h>
#include <mma.h>
#include <cstdint>

using namespace nvcuda;

// Problem constants (fixed by dataset)
#define DFEAT 512
#define NOUT  64
#define GROWS 96              // gemm rows per block
#define MAXN  100032          // N_NODES rounded up: divisible by 96 (96*1042)
#define NPAD  102400          // node arrays padded to 1024*100 for scan tiles
#define MAXE  1600000
#define NBLK_SCAN 100         // NPAD / 1024
#define WSPLIT_BLKS 128       // 32768 W elements / 256

// Static device scratch (no runtime allocation allowed).
// INVARIANT: g_cnt and g_tilestate are ZERO at entry of every call — they are
// zero-initialized at module load, and every call re-zeros them in the fused
// kernel (slot 3) after scan (their last reader) is done. Deterministic.
__device__ float          g_h[(size_t)MAXN * NOUT];   // projected features (25.6 MB)
__device__ __nv_bfloat16  g_Wh16[DFEAT * NOUT];       // W hi bf16, [k][n]
__device__ __nv_bfloat16  g_Wl16[DFEAT * NOUT];       // W lo residual bf16, [k][n]
__device__ uint2          g_pairs[MAXE];              // (src, w-bits) grouped by dst
__device__ int            g_cnt[NPAD];                // per-dst degree
__device__ int            g_start[NPAD];              // CSR row start
__device__ int            g_cursor[NPAD];             // fill cursor == row end
__device__ unsigned int   g_tilestate[NBLK_SCAN];     // lookback: flag<<30 | sum

// ---------------------------------------------------------------------------
// Slot 1: fused W-split + dst-degree histogram (independent works, one launch)
// blocks [0, WSPLIT_BLKS): split W;  rest: histogram (4 edges/thread, int4).
// g_cnt is zero at entry per the invariant above.
// ---------------------------------------------------------------------------
__global__ void __launch_bounds__(256) setup_hist_kernel(const float* __restrict__ W,
                                                         const int*   __restrict__ edst,
                                                         int n_edges)
{
    if (blockIdx.x < WSPLIT_BLKS) {
        int i = blockIdx.x * 256 + threadIdx.x;          // < 32768 always
        float w = __ldg(&W[i]);
        uint32_t u = __float_as_uint(w);
        unsigned short hb = (unsigned short)(u >> 16);   // truncated bf16
        g_Wh16[i] = *reinterpret_cast<__nv_bfloat16*>(&hb);
        float lo = w - __uint_as_float(u & 0xFFFF0000u);
        g_Wl16[i] = __float2bfloat16_rn(lo);
    } else {
        int t = (blockIdx.x - WSPLIT_BLKS) * 256 + threadIdx.x;
        int e = t * 4;
        if (e + 3 < n_edges) {
            int4 d = *(const int4*)(edst + e);
            atomicAdd(&g_cnt[d.x], 1);
            atomicAdd(&g_cnt[d.y], 1);
            atomicAdd(&g_cnt[d.z], 1);
            atomicAdd(&g_cnt[d.w], 1);
        } else {
            for (int k = e; k < n_edges; ++k) atomicAdd(&g_cnt[__ldg(&edst[k])], 1);
        }
    }
}

// ---------------------------------------------------------------------------
// Slot 2: single-pass exclusive scan (decoupled lookback), 1024 nodes/block.
// ---------------------------------------------------------------------------
__global__ void __launch_bounds__(256) scan_onepass_kernel() {
    const int b   = blockIdx.x;
    const int tid = threadIdx.x;
    const int idx = b * 1024 + tid * 4;

    int4 c = *(const int4*)&g_cnt[idx];
    int t = c.x + c.y + c.z + c.w;

    int incl = t;
#pragma unroll
    for (int o = 1; o < 32; o <<= 1) {
        int u = __shfl_up_sync(0xffffffffu, incl, o);
        if ((tid & 31) >= o) incl += u;
    }
    __shared__ int wsum[8];
    __shared__ int s_excl;
    if ((tid & 31) == 31) wsum[tid >> 5] = incl;
    __syncthreads();

    const int wid = tid >> 5;
    int off = 0, agg = 0;
#pragma unroll
    for (int i = 0; i < 8; ++i) {
        int v = wsum[i];
        if (i < wid) off += v;
        agg += v;
    }

    if (tid == 0) {
        if (b == 0) {
            atomicExch(&g_tilestate[0], (2u << 30) | (unsigned)agg);
            s_excl = 0;
        } else {
            atomicExch(&g_tilestate[b], (1u << 30) | (unsigned)agg);
            int run = 0, p = b - 1;
            while (true) {
                unsigned s;
                do { s = atomicAdd(&g_tilestate[p], 0u); } while ((s >> 30) == 0u);
                run += (int)(s & 0x3fffffffu);
                if ((s >> 30) == 2u) break;
                --p;
            }
            atomicExch(&g_tilestate[b], (2u << 30) | (unsigned)(run + agg));
            s_excl = run;
        }
    }
    __syncthreads();

    int s0 = s_excl + (incl - t) + off;
    int4 st;
    st.x = s0; st.y = s0 + c.x; st.z = st.y + c.y; st.w = st.z + c.z;
    *(int4*)&g_start[idx]  = st;
    *(int4*)&g_cursor[idx] = st;
}

// ---------------------------------------------------------------------------
// pack2: (f0,f1) -> packed bf16x2 hi (truncated, via PRMT) + bf16x2 lo
// ---------------------------------------------------------------------------
__device__ __forceinline__ void pack2(float f0, float f1, uint32_t& hp, uint32_t& lp) {
    uint32_t u0 = __float_as_uint(f0), u1 = __float_as_uint(f1);
    hp = __byte_perm(u0, u1, 0x7632);                 // (hi16(f0), hi16(f1))
    float l0 = f0 - __uint_as_float(u0 & 0xFFFF0000u);
    float l1 = f1 - __uint_as_float(u1 & 0xFFFF0000u);
    __nv_bfloat162 l2 = __floats2bfloat162_rn(l0, l1);
    lp = *reinterpret_cast<uint32_t*>(&l2);
}

// ---------------------------------------------------------------------------
// Slot 3: FUSED gemm + reorder + state-reset by blockIdx range.
//   [0, ngemm):                     R11 GEMM body (96x64 tile, split-bf16 HMMA)
//   [ngemm, ngemm+nreo):            reorder (2 edges/thread, 192 threads)
//   [ngemm+nreo, +ZBLKS):           zero g_cnt/g_tilestate for the NEXT call
// GEMM is latency-bound (issue 28%, L2 17%); reorder is L2-bound (issue 3.4%)
// -> co-scheduling hides reorder's 25.6us under the GEMM.
// ---------------------------------------------------------------------------
__global__ void __launch_bounds__(192, 3) fused_kernel(const float* __restrict__ x,
                                                       const int*   __restrict__ esrc,
                                                       const int*   __restrict__ edst,
                                                       const float* __restrict__ ew,
                                                       int n_rows, int n_edges,
                                                       int ngemm, int nreo)
{
    if (blockIdx.x >= ngemm) {
        int rb = blockIdx.x - ngemm;
        if (rb < nreo) {
            // ---- reorder: edges -> dst-grouped (src, w) pairs ----
            int t = rb * 192 + threadIdx.x;
            int e = t * 2;
            if (e + 1 < n_edges) {
                int2   s = *(const int2*)(esrc + e);
                int2   d = *(const int2*)(edst + e);
                float2 w = *(const float2*)(ew + e);
                int p0 = atomicAdd(&g_cursor[d.x], 1);
                g_pairs[p0] = make_uint2((unsigned)s.x, __float_as_uint(w.x));
                int p1 = atomicAdd(&g_cursor[d.y], 1);
                g_pairs[p1] = make_uint2((unsigned)s.y, __float_as_uint(w.y));
            } else if (e < n_edges) {
                int d = __ldg(&edst[e]);
                int pos = atomicAdd(&g_cursor[d], 1);
                g_pairs[pos] = make_uint2((unsigned)__ldg(&esrc[e]),
                                          __float_as_uint(__ldg(&ew[e])));
            }
        } else {
            // ---- reset g_cnt / g_tilestate for the next call (scan is done) ----
            int idx = (rb - nreo) * 192 + threadIdx.x;
            if (idx < NPAD / 4) ((int4*)g_cnt)[idx] = make_int4(0, 0, 0, 0);
            if (idx < NBLK_SCAN) g_tilestate[idx] = 0u;
        }
        return;
    }

    // ---- GEMM body (exact R11 config: 106.6us, 96 regs, 3 CTAs/SM) ----
    __shared__ __align__(16) __nv_bfloat16 xs_hi[GROWS][40];  // 96 rows x 32 k (+pad)
    __shared__ __align__(16) __nv_bfloat16 xs_lo[GROWS][40];
    __shared__ __align__(16) __nv_bfloat16 ws_hi[32][72];     // 32 k x 64 n (+pad)
    __shared__ __align__(16) __nv_bfloat16 ws_lo[32][72];

    const int tid  = threadIdx.x;
    const int row0 = blockIdx.x * GROWS;

    const int wid    = tid >> 5;
    const int warp_r = (wid >> 1) * 32;   // 0,32,64
    const int warp_c = (wid & 1) * 32;    // 0,32

    wmma::fragment<wmma::accumulator, 16, 16, 16, float> acc[2][2];
#pragma unroll
    for (int i = 0; i < 2; ++i)
#pragma unroll
        for (int j = 0; j < 2; ++j)
            wmma::fill_fragment(acc[i][j], 0.0f);

    // x loader mapping: 768 float4 per tile (96 rows x 8), 4 per thread.
    float4 xv[4];
    int  xrow[4];
#pragma unroll
    for (int p = 0; p < 4; ++p) {
        int f = tid + p * 192;
        int r = f >> 3;
        int gr = row0 + r;
        if (gr >= n_rows) gr = n_rows - 1;           // clamp: dup rows, never gathered
        xrow[p] = gr;
        xv[p] = *(const float4*)(x + (size_t)gr * DFEAT + (f & 7) * 4);
    }

    const int KT = DFEAT / 32;
    for (int kt = 0; kt < KT; ++kt) {
        // stage x: truncation split + packed 8B stores
#pragma unroll
        for (int p = 0; p < 4; ++p) {
            int f = tid + p * 192;
            int r = f >> 3;
            int k4 = (f & 7) * 4;
            uint32_t h0, l0, h1, l1;
            pack2(xv[p].x, xv[p].y, h0, l0);
            pack2(xv[p].z, xv[p].w, h1, l1);
            *(uint2*)&xs_hi[r][k4] = make_uint2(h0, h1);
            *(uint2*)&xs_lo[r][k4] = make_uint2(l0, l1);
        }
        // stage W via cp.async: 512 16B chunks (256 hi + 256 lo)
        for (int g = tid; g < 512; g += 192) {
            int hi = (g < 256);
            int gg = g & 255;
            int r  = gg >> 3;                 // k row 0..31
            int c8 = (gg & 7) * 8;            // 8 bf16 per chunk
            const __nv_bfloat16* src = (hi ? g_Wh16 : g_Wl16) + (size_t)(kt * 32 + r) * NOUT + c8;
            __nv_bfloat16* dst = (hi ? &ws_hi[r][c8] : &ws_lo[r][c8]);
            __pipeline_memcpy_async(dst, src, 16);
        }
        __pipeline_commit();

        // prefetch next x tile into registers (overlaps cp.async)
        if (kt + 1 < KT) {
#pragma unroll
            for (int p = 0; p < 4; ++p) {
                int f = tid + p * 192;
                xv[p] = *(const float4*)(x + (size_t)xrow[p] * DFEAT + (kt + 1) * 32 + (f & 7) * 4);
            }
        }

        __pipeline_wait_prior(0);
        __syncthreads();

#pragma unroll
        for (int ks = 0; ks < 2; ++ks) {
            const int k0 = ks * 16;
            wmma::fragment<wmma::matrix_a, 16, 16, 16, __nv_bfloat16, wmma::row_major> a_hi[2], a_lo[2];
#pragma unroll
            for (int i = 0; i < 2; ++i) {
                wmma::load_matrix_sync(a_hi[i], &xs_hi[warp_r + i * 16][k0], 40);
                wmma::load_matrix_sync(a_lo[i], &xs_lo[warp_r + i * 16][k0], 40);
            }
#pragma unroll
            for (int j = 0; j < 2; ++j) {
                wmma::fragment<wmma::matrix_b, 16, 16, 16, __nv_bfloat16, wmma::row_major> b_hi, b_lo;
                wmma::load_matrix_sync(b_hi, &ws_hi[k0][warp_c + j * 16], 72);
                wmma::load_matrix_sync(b_lo, &ws_lo[k0][warp_c + j * 16], 72);
#pragma unroll
                for (int i = 0; i < 2; ++i) {
                    wmma::mma_sync(acc[i][j], a_hi[i], b_hi, acc[i][j]);
                    wmma::mma_sync(acc[i][j], a_hi[i], b_lo, acc[i][j]);
                    wmma::mma_sync(acc[i][j], a_lo[i], b_hi, acc[i][j]);
                }
            }
        }
        __syncthreads();
    }

    // g_h padded to MAXN (multiple of 96): full-tile stores stay in bounds.
#pragma unroll
    for (int i = 0; i < 2; ++i)
#pragma unroll
        for (int j = 0; j < 2; ++j)
            wmma::store_matrix_sync(
                g_h + (size_t)(row0 + warp_r + i * 16) * NOUT + warp_c + j * 16,
                acc[i][j], NOUT, wmma::mem_row_major);
}

// ---------------------------------------------------------------------------
// Slot 4 (profiled): gather + fused softmax. One warp per dst node.
// ---------------------------------------------------------------------------
__global__ void __launch_bounds__(256) gather_softmax_kernel(float* __restrict__ out,
                                                             int n_nodes)
{
    int node = blockIdx.x * 8 + (threadIdx.x >> 5);
    int lane = threadIdx.x & 31;
    if (node >= n_nodes) return;

    int start = __ldg(&g_start[node]);
    int end   = __ldg(&g_cursor[node]);

    float2 acc = make_float2(0.f, 0.f);

    for (int base = start; base < end; base += 32) {
        int idx = base + lane;
        uint2 pr = make_uint2(0u, 0u);
        if (idx < end) pr = __ldg(&g_pairs[idx]);
        int m = end - base; if (m > 32) m = 32;

        int j = 0;
        for (; j + 8 <= m; j += 8) {
#pragma unroll
            for (int u = 0; u < 8; ++u) {
                int   ss = __shfl_sync(0xffffffffu, (int)pr.x, j + u);
                float sw = __uint_as_float(__shfl_sync(0xffffffffu, pr.y, j + u));
                float2 hv = *(const float2*)(g_h + (size_t)ss * NOUT + (lane << 1));
                acc.x = fmaf(sw, hv.x, acc.x);
                acc.y = fmaf(sw, hv.y, acc.y);
            }
        }
        for (; j < m; ++j) {
            int   ss = __shfl_sync(0xffffffffu, (int)pr.x, j);
            float sw = __uint_as_float(__shfl_sync(0xffffffffu, pr.y, j));
            float2 hv = *(const float2*)(g_h + (size_t)ss * NOUT + (lane << 1));
            acc.x = fmaf(sw, hv.x, acc.x);
            acc.y = fmaf(sw, hv.y, acc.y);
        }
    }

    float mx = fmaxf(acc.x, acc.y);
#pragma unroll
    for (int o = 16; o > 0; o >>= 1)
        mx = fmaxf(mx, __shfl_xor_sync(0xffffffffu, mx, o));

    float e0 = __expf(acc.x - mx);
    float e1 = __expf(acc.y - mx);
    float s = e0 + e1;
#pragma unroll
    for (int o = 16; o > 0; o >>= 1)
        s += __shfl_xor_sync(0xffffffffu, s, o);

    float inv = 1.0f / s;
    *(float2*)&out[(size_t)node * NOUT + (lane << 1)] = make_float2(e0 * inv, e1 * inv);
}

// ---------------------------------------------------------------------------
// Launch. Input order per metadata: x, edge_src, edge_dst, edge_w, W.
// 4 launches: (Wsplit+hist) -> scan -> (gemm||reorder||zero) -> gather.
// gather sits at capture slot 4 for profiling this round.
// ---------------------------------------------------------------------------
extern "C" void kernel_launch(void* const* d_in, const int* in_sizes, int n_in,
                              void* d_out, int out_size)
{
    const float* x    = (const float*)d_in[0];
    const int*   esrc = (const int*)  d_in[1];
    const int*   edst = (const int*)  d_in[2];
    const float* ew   = (const float*)d_in[3];
    const float* W    = (const float*)d_in[4];
    float*       out  = (float*)d_out;

    const int n_nodes = in_sizes[0] / DFEAT;
    const int n_edges = in_sizes[1];
    const int ntiles  = (n_nodes + 1023) / 1024;
    const int hblk    = (n_edges + 1023) / 1024;           // 4 edges/thread, 256 thr
    const int ngemm   = (n_nodes + GROWS - 1) / GROWS;     // 1042
    const int nreo    = (n_edges + 383) / 384;             // 2 edges/thread, 192 thr
    const int nzero   = (NPAD / 4 + 191) / 192;            // 134

    setup_hist_kernel<<<WSPLIT_BLKS + hblk, 256>>>(W, edst, n_edges);        // 1
    scan_onepass_kernel<<<ntiles, 256>>>();                                  // 2
    fused_kernel<<<ngemm + nreo + nzero, 192>>>(x, esrc, edst, ew,
                                                n_nodes, n_edges,
                                                ngemm, nreo);                // 3
    gather_softmax_kernel<<<(n_nodes + 7) / 8, 256>>>(out, n_nodes);         // 4 (profiled)
}